// round 9
// baseline (speedup 1.0000x reference)
#include <cuda_runtime.h>
#include <math.h>

#define N 1536
#define EE 24576
#define E2 (EE + N)
#define HD 128
#define DD 1280
#define NW 48   // N/32 bitmask words per row
#define ZU 20   // split-K depth for U

// ---------------- device scratch (no allocations allowed) ----------------
// Invariants across runs: g_cntT/g_cntS zero at entry (re-zeroed in kFill);
// g_B zeroed by kZero (event-ordered before kFill).
__device__ float g_wa[HD], g_wb[HD], g_c2[N];
__device__ float g_sa[N], g_da[N];
__device__ float g_U[HD * N];
__device__ float g_Up[ZU * HD * N];
__device__ float g_xg[N * HD];
__device__ float g_H2[N * N];
__device__ float g_H2b[N * N];
__device__ int   g_cntT[N], g_offT[N + 1], g_curT[N];
__device__ int   g_cntS[N], g_offS[N + 1], g_curS[N];
__device__ int   g_srcT[E2];
__device__ int   g_tgtS[EE];
__device__ unsigned g_B[N * NW];
__device__ unsigned g_Mb[N * NW];     // final 2-hop masks (fully rewritten each run)

__device__ __forceinline__ float lrelu(float v) { return v > 0.f ? v : 0.2f * v; }
__device__ __forceinline__ unsigned fenc(float f) {
  unsigned u = __float_as_uint(f);
  return (u & 0x80000000u) ? ~u : (u | 0x80000000u);
}

__device__ __forceinline__ float blockSum256(float v, float* sh) {
  __syncthreads();
  #pragma unroll
  for (int o = 16; o; o >>= 1) v += __shfl_xor_sync(0xFFFFFFFFu, v, o);
  if ((threadIdx.x & 31) == 0) sh[threadIdx.x >> 5] = v;
  __syncthreads();
  if (threadIdx.x < 32) {
    v = (threadIdx.x < 8) ? sh[threadIdx.x] : 0.f;
    #pragma unroll
    for (int o = 4; o; o >>= 1) v += __shfl_xor_sync(0xFFFFFFFFu, v, o);
  }
  return v;
}

// ---------- host-side fork/join resources ----------
struct HxStreams {
  cudaStream_t s1, s2, s3;
  cudaEvent_t e0, e1, e2, e3, e4, eF;
  HxStreams() {
    cudaStreamCreateWithFlags(&s1, cudaStreamNonBlocking);
    cudaStreamCreateWithFlags(&s2, cudaStreamNonBlocking);
    cudaStreamCreateWithFlags(&s3, cudaStreamNonBlocking);
    cudaEventCreateWithFlags(&e0, cudaEventDisableTiming);
    cudaEventCreateWithFlags(&e1, cudaEventDisableTiming);
    cudaEventCreateWithFlags(&e2, cudaEventDisableTiming);
    cudaEventCreateWithFlags(&e3, cudaEventDisableTiming);
    cudaEventCreateWithFlags(&e4, cudaEventDisableTiming);
    cudaEventCreateWithFlags(&eF, cudaEventDisableTiming);
  }
};
static HxStreams g_hs;

// ============ kZero: zero out buffer + g_B ===============
__global__ void kZero(float* __restrict__ out, int out_size) {
  int i = blockIdx.x * blockDim.x + threadIdx.x;
  int stride = gridDim.x * blockDim.x;
  for (int p = i; p < out_size; p += stride) out[p] = 0.f;
  for (int p = i; p < N * NW; p += stride) g_B[p] = 0u;
}

// ============ kCount ===================================
__global__ void kCount(const int* __restrict__ ei) {
  int idx = blockIdx.x * blockDim.x + threadIdx.x;
  if (idx < EE) {
    atomicAdd(&g_cntS[ei[idx]], 1);
    atomicAdd(&g_cntT[ei[EE + idx]], 1);
  } else if (idx < E2) {
    atomicAdd(&g_cntT[idx - EE], 1);
  }
}

// ============ kScan ========================
__global__ void kScan() {
  __shared__ int part[256];
  int tid = threadIdx.x;
  int base = tid * 6;
  {
    int a[6]; int s = 0;
    #pragma unroll
    for (int u = 0; u < 6; u++) { a[u] = g_cntT[base + u]; s += a[u]; }
    part[tid] = s;
    __syncthreads();
    for (int o = 1; o < 256; o <<= 1) {
      int v = (tid >= o) ? part[tid - o] : 0;
      __syncthreads();
      part[tid] += v;
      __syncthreads();
    }
    int excl = part[tid] - s;
    #pragma unroll
    for (int u = 0; u < 6; u++) {
      g_offT[base + u] = excl; g_curT[base + u] = excl; excl += a[u];
    }
    if (tid == 255) g_offT[N] = part[255];
    __syncthreads();
  }
  {
    int a[6]; int s = 0;
    #pragma unroll
    for (int u = 0; u < 6; u++) { a[u] = g_cntS[base + u]; s += a[u]; }
    part[tid] = s;
    __syncthreads();
    for (int o = 1; o < 256; o <<= 1) {
      int v = (tid >= o) ? part[tid - o] : 0;
      __syncthreads();
      part[tid] += v;
      __syncthreads();
    }
    int excl = part[tid] - s;
    #pragma unroll
    for (int u = 0; u < 6; u++) {
      g_offS[base + u] = excl; g_curS[base + u] = excl; excl += a[u];
    }
    if (tid == 255) g_offS[N] = part[255];
  }
}

// ============ kFill: CSR fill + B build + cnt re-zero ======================
__global__ void kFill(const int* __restrict__ ei) {
  int idx = blockIdx.x * blockDim.x + threadIdx.x;
  if (idx < N) { g_cntT[idx] = 0; g_cntS[idx] = 0; }
  if (idx >= E2) return;
  int s, t;
  if (idx < EE) { s = ei[idx]; t = ei[EE + idx]; }
  else { s = t = idx - EE; }
  int pos = atomicAdd(&g_curT[t], 1);
  g_srcT[pos] = s;
  if (idx < EE) {
    int ps = atomicAdd(&g_curS[s], 1);
    g_tgtS[ps] = t;
    atomicOr(&g_B[t * NW + (s >> 5)], 1u << (s & 31));
  }
}

// ============ kVec1 ============================
__global__ __launch_bounds__(256) void kVec1(const float* __restrict__ W1,
                                             const float* __restrict__ a1,
                                             const float* __restrict__ a2,
                                             const float* __restrict__ b1,
                                             const float* __restrict__ w2,
                                             const float* __restrict__ xo) {
  __shared__ float sh[8];
  int b = blockIdx.x, tid = threadIdx.x;
  if (b < HD) {
    float s1 = 0.f, s2 = 0.f;
    for (int d = tid; d < DD; d += 256) {
      float w = W1[b * DD + d];
      s1 += w * a1[d]; s2 += w * a2[d];
    }
    float r1 = blockSum256(s1, sh);
    float r2 = blockSum256(s2, sh);
    if (tid == 0) { g_wa[b] = r1; g_wb[b] = r2; }
  } else {
    int j = b - HD;
    float s = 0.f;
    for (int d = tid; d < DD; d += 256) s += b1[d] * w2[d] * xo[j * DD + d];
    float r = blockSum256(s, sh);
    if (tid == 0) g_c2[j] = r;
  }
}

// ============ kSada ==================================
__global__ __launch_bounds__(256) void kSada(const float* __restrict__ x) {
  int node = blockIdx.x * 8 + (threadIdx.x >> 5);
  int lane = threadIdx.x & 31;
  if (node >= N) return;
  float s1 = 0.f, s2 = 0.f;
  #pragma unroll
  for (int k = lane; k < HD; k += 32) {
    float xv = x[node * HD + k];
    s1 += xv * g_wa[k]; s2 += xv * g_wb[k];
  }
  #pragma unroll
  for (int o = 16; o; o >>= 1) {
    s1 += __shfl_xor_sync(0xFFFFFFFFu, s1, o);
    s2 += __shfl_xor_sync(0xFFFFFFFFu, s2, o);
  }
  if (lane == 0) { g_sa[node] = s1; g_da[node] = s2; }
}

// ============ kUp: U split-K partials ====================
__global__ __launch_bounds__(256, 2) void kUp(const float* __restrict__ W1,
                                              const float* __restrict__ w2,
                                              const float* __restrict__ xo) {
  __shared__ float As[2][16][65];
  __shared__ float Bs[2][16][129];
  int b = blockIdx.x;
  int tileid = b % 24;
  int z = b / 24;
  int j0 = (tileid % 12) * 128;
  int m0 = (tileid / 12) * 64;
  int k0 = z * 64;
  int tid = threadIdx.x, tx = tid & 15, ty = tid >> 4;
  float acc[4][8];
  #pragma unroll
  for (int u = 0; u < 4; u++)
    #pragma unroll
    for (int w = 0; w < 8; w++) acc[u][w] = 0.f;
  auto load = [&](int buf, int kc) {
    #pragma unroll
    for (int l = tid; l < 64 * 16; l += 256) {
      int k = l & 15, m = l >> 4;
      As[buf][k][m] = W1[(m0 + m) * DD + k0 + kc + k] * w2[k0 + kc + k];
    }
    #pragma unroll
    for (int l = tid; l < 128 * 16; l += 256) {
      int k = l & 15, j = l >> 4;
      Bs[buf][k][j] = xo[(j0 + j) * DD + k0 + kc + k];
    }
  };
  load(0, 0);
  __syncthreads();
  for (int c = 0; c < 4; c++) {
    int buf = c & 1;
    if (c < 3) load(buf ^ 1, (c + 1) * 16);
    #pragma unroll
    for (int kk = 0; kk < 16; kk++) {
      float ra[4], rb[8];
      #pragma unroll
      for (int u = 0; u < 4; u++) ra[u] = As[buf][kk][u * 16 + ty];
      #pragma unroll
      for (int w = 0; w < 8; w++) rb[w] = Bs[buf][kk][w * 16 + tx];
      #pragma unroll
      for (int u = 0; u < 4; u++)
        #pragma unroll
        for (int w = 0; w < 8; w++) acc[u][w] += ra[u] * rb[w];
    }
    __syncthreads();
  }
  float* Up = g_Up + z * (HD * N);
  #pragma unroll
  for (int u = 0; u < 4; u++)
    #pragma unroll
    for (int w = 0; w < 8; w++)
      Up[(m0 + u * 16 + ty) * N + j0 + w * 16 + tx] = acc[u][w];
}

// ============ kUred ===============================
__global__ void kUred() {
  int idx = blockIdx.x * blockDim.x + threadIdx.x;
  float s = 0.f;
  #pragma unroll
  for (int z = 0; z < ZU; z++) s += g_Up[z * (HD * N) + idx];
  g_U[idx] = s;
}

// ============ kXg: fused GAT-1 softmax + xg = P@x ==========================
__global__ __launch_bounds__(128) void kXg(const float* __restrict__ x) {
  int t = blockIdx.x, tid = threadIdx.x;
  __shared__ int   ss[256];
  __shared__ float sw[256];
  __shared__ float sh[4];
  int p0 = g_offT[t], p1 = g_offT[t + 1];
  float dt = g_da[t];
  float m = -3.4e38f;
  for (int p = p0 + tid; p < p1; p += 128)
    m = fmaxf(m, lrelu(g_sa[g_srcT[p]] + dt));
  #pragma unroll
  for (int o = 16; o; o >>= 1) m = fmaxf(m, __shfl_xor_sync(0xFFFFFFFFu, m, o));
  if ((tid & 31) == 0) sh[tid >> 5] = m;
  __syncthreads();
  m = fmaxf(fmaxf(sh[0], sh[1]), fmaxf(sh[2], sh[3]));
  float acc = 0.f, dsum = 0.f;
  for (int base = p0; base < p1; base += 256) {
    int nc = min(256, p1 - base);
    for (int q = tid; q < nc; q += 128) {
      int s = g_srcT[base + q];
      float w = expf(lrelu(g_sa[s] + dt) - m);
      ss[q] = s;
      sw[q] = w;
      dsum += w;
    }
    __syncthreads();
    for (int q = 0; q < nc; q++)
      acc += sw[q] * x[ss[q] * HD + tid];
    __syncthreads();
  }
  float den = dsum;
  #pragma unroll
  for (int o = 16; o; o >>= 1) den += __shfl_xor_sync(0xFFFFFFFFu, den, o);
  if ((tid & 31) == 0) sh[tid >> 5] = den;
  __syncthreads();
  den = sh[0] + sh[1] + sh[2] + sh[3];
  g_xg[t * HD + tid] = acc / den;
}

// ============ kH2: H2 partials = xg @ U (split-K=2) ==========
__global__ __launch_bounds__(256, 2) void kH2() {
  __shared__ float As[2][16][65];
  __shared__ float Bs[2][16][129];
  int b = blockIdx.x;
  int tile = b % 288;
  int z = b / 288;
  int j0 = (tile % 12) * 128;
  int m0 = (tile / 12) * 64;
  int k0 = z * 64;
  int tid = threadIdx.x, tx = tid & 15, ty = tid >> 4;
  float acc[4][8];
  #pragma unroll
  for (int u = 0; u < 4; u++)
    #pragma unroll
    for (int w = 0; w < 8; w++) acc[u][w] = 0.f;
  auto load = [&](int buf, int kc) {
    #pragma unroll
    for (int l = tid; l < 64 * 16; l += 256) {
      int k = l & 15, m = l >> 4;
      As[buf][k][m] = g_xg[(m0 + m) * HD + k0 + kc + k];
    }
    #pragma unroll
    for (int l = tid; l < 16 * 128; l += 256) {
      int j = l & 127, k = l >> 7;
      Bs[buf][k][j] = g_U[(k0 + kc + k) * N + j0 + j];
    }
  };
  load(0, 0);
  __syncthreads();
  for (int c = 0; c < 4; c++) {
    int buf = c & 1;
    if (c < 3) load(buf ^ 1, (c + 1) * 16);
    #pragma unroll
    for (int kk = 0; kk < 16; kk++) {
      float ra[4], rb[8];
      #pragma unroll
      for (int u = 0; u < 4; u++) ra[u] = As[buf][kk][u * 16 + ty];
      #pragma unroll
      for (int w = 0; w < 8; w++) rb[w] = Bs[buf][kk][w * 16 + tx];
      #pragma unroll
      for (int u = 0; u < 4; u++)
        #pragma unroll
        for (int w = 0; w < 8; w++) acc[u][w] += ra[u] * rb[w];
    }
    __syncthreads();
  }
  float* outp = z ? g_H2b : g_H2;
  #pragma unroll
  for (int u = 0; u < 4; u++)
    #pragma unroll
    for (int w = 0; w < 8; w++)
      outp[(m0 + u * 16 + ty) * N + j0 + w * 16 + tx] = acc[u][w];
}

// ============ kMb: per-row 2-hop mask (off critical path) ==================
__global__ __launch_bounds__(256) void kMb() {
  int i = blockIdx.x, tid = threadIdx.x;
  __shared__ unsigned mb[NW];
  __shared__ int klist[N];
  __shared__ int wcnt[NW + 1];
  if (tid < NW) {
    unsigned w = g_B[i * NW + tid];
    if (tid == (i >> 5)) w |= 1u << (i & 31);
    mb[tid] = w;
  }
  __syncthreads();
  if (tid < NW) wcnt[tid] = __popc(mb[tid]);
  __syncthreads();
  if (tid == 0) {
    int s = 0;
    for (int w = 0; w < NW; w++) { int c = wcnt[w]; wcnt[w] = s; s += c; }
    wcnt[NW] = s;
  }
  __syncthreads();
  int nk = wcnt[NW];
  if (tid < NW) {
    unsigned b = mb[tid]; int o = wcnt[tid];
    while (b) { int t = __ffs(b) - 1; b &= b - 1; klist[o++] = tid * 32 + t; }
  }
  __syncthreads();
  if (tid < 4 * NW) {
    int sy = tid / NW, cx = tid % NW;
    unsigned acc = 0u;
    for (int q = sy; q < nk; q += 4) acc |= g_B[klist[q] * NW + cx];
    atomicOr(&mb[cx], acc);
  }
  __syncthreads();
  if (tid < NW) g_Mb[i * NW + tid] = mb[tid];
}

// == kF: warp-per-target gather softmax + radix-select + output =============
__global__ __launch_bounds__(256) void kF(const float* __restrict__ pas2,
                                          const float* __restrict__ pad2,
                                          const float* __restrict__ pb2,
                                          float* __restrict__ out, int wk) {
  int i = blockIdx.x, tid = threadIdx.x;
  int lane = tid & 31, wid = tid >> 5;
  __shared__ float v[N];
  __shared__ int vlist[N];
  __shared__ float scl[N];
  __shared__ unsigned k32[N];
  __shared__ unsigned mb[NW];
  __shared__ int wcnt[NW + 1];
  __shared__ int hist[256];
  __shared__ unsigned s_pfx;
  __shared__ int s_rem;

  float as2 = pas2[0], ad2 = pad2[0], b2 = pb2[0];

  if (tid < NW) mb[tid] = g_Mb[i * NW + tid];
  // vectorized v load: v = H2 + H2b + c2
  {
    const float4* h2a = (const float4*)(g_H2 + i * N);
    const float4* h2b = (const float4*)(g_H2b + i * N);
    const float4* c2v = (const float4*)g_c2;
    float4* vv = (float4*)v;
    for (int j = tid; j < N / 4; j += 256) {
      float4 a = h2a[j], b = h2b[j], c = c2v[j];
      vv[j] = make_float4(a.x + b.x + c.x, a.y + b.y + c.y,
                          a.z + b.z + c.z, a.w + b.w + c.w);
    }
  }
  __syncthreads();
  if (tid < NW) wcnt[tid] = __popc(mb[tid]);
  __syncthreads();
  if (tid == 0) {
    int s = 0;
    for (int w = 0; w < NW; w++) { int c = wcnt[w]; wcnt[w] = s; s += c; }
    wcnt[NW] = s;
  }
  __syncthreads();
  int nvv = wcnt[NW];
  if (tid < NW) {
    unsigned b = mb[tid]; int o = wcnt[tid];
    while (b) { int t = __ffs(b) - 1; b &= b - 1; vlist[o++] = tid * 32 + t; }
  }
  __syncthreads();
  // warp-per-target gather softmax (coalesced CSR reads)
  for (int li = wid; li < nvv; li += 8) {
    int t = vlist[li];
    int p0 = g_offT[t], p1 = g_offT[t + 1];
    float adt = ad2 * v[t];
    float m = -3.4e38f;
    for (int p = p0 + lane; p < p1; p += 32) {
      int s = g_srcT[p];
      if ((mb[s >> 5] >> (s & 31)) & 1u)
        m = fmaxf(m, lrelu(fmaf(as2, v[s], adt)));
    }
    #pragma unroll
    for (int o = 16; o; o >>= 1) m = fmaxf(m, __shfl_xor_sync(0xFFFFFFFFu, m, o));
    float den = 0.f, num = 0.f;
    for (int p = p0 + lane; p < p1; p += 32) {
      int s = g_srcT[p];
      if ((mb[s >> 5] >> (s & 31)) & 1u) {
        float vs = v[s];
        float w = expf(lrelu(fmaf(as2, vs, adt)) - m);
        den += w;
        num += w * vs;
      }
    }
    #pragma unroll
    for (int o = 16; o; o >>= 1) {
      den += __shfl_xor_sync(0xFFFFFFFFu, den, o);
      num += __shfl_xor_sync(0xFFFFFFFFu, num, o);
    }
    if (lane == 0) {
      float sc = num / fmaxf(den, 1e-12f) + b2;
      scl[li] = sc;
      k32[li] = fenc(sc);
    }
  }
  int kk = (nvv + 1) >> 1;
  if (tid == 0) { s_rem = kk; s_pfx = 0u; }
  __syncthreads();
  // radix-select the kk-th largest key
  for (int r = 0; r < 4; r++) {
    int shift = 24 - 8 * r;
    hist[tid] = 0;
    __syncthreads();
    unsigned pfx = s_pfx;
    for (int li = tid; li < nvv; li += 256) {
      unsigned key = k32[li];
      bool cand = (r == 0) || ((key >> (shift + 8)) == pfx);
      if (cand) atomicAdd(&hist[(key >> shift) & 255], 1);
    }
    __syncthreads();
    if (tid < 32) {
      int s = 0;
      #pragma unroll
      for (int u = 0; u < 8; u++) s += hist[tid * 8 + u];
      int cum = s;
      #pragma unroll
      for (int o = 1; o < 32; o <<= 1) {
        int t2 = __shfl_down_sync(0xFFFFFFFFu, cum, o);
        if (tid + o < 32) cum += t2;
      }
      int run = cum - s;
      int rem = s_rem;
      unsigned pfxold = s_pfx;
      int fb = -1, frem = 0;
      for (int bb = tid * 8 + 7; bb >= tid * 8; bb--) {
        int h = hist[bb];
        if (run < rem && rem <= run + h) { fb = bb; frem = rem - run; }
        run += h;
      }
      __syncwarp();
      if (fb >= 0) { s_pfx = (pfxold << 8) | (unsigned)fb; s_rem = frem; }
    }
    __syncthreads();
  }
  unsigned T = s_pfx;
  int rem = s_rem;
  for (int li = tid; li < nvv; li += 256) {
    unsigned key = k32[li];
    bool keep = key > T;
    if (!keep && key == T) {
      int cnt = 0;
      for (int l2 = 0; l2 < li; l2++) cnt += (k32[l2] == T);
      keep = cnt < rem;
    }
    if (keep) {
      int j = vlist[li];
      float sj = scl[li];
      out[i * N + j] = 1.f / (1.f + expf(-sj));
      if (wk) out[N * N + i * N + j] = 1.f;
    }
  }
}

// ---------------- launch: forked-capture graph ----------------
extern "C" void kernel_launch(void* const* d_in, const int* in_sizes, int n_in,
                              void* d_out, int out_size) {
  const float* x   = (const float*)d_in[0];
  const float* xo  = (const float*)d_in[1];
  const int*   ei  = (const int*)d_in[2];
  const float* W1  = (const float*)d_in[4];
  const float* a1  = (const float*)d_in[5];
  const float* a2  = (const float*)d_in[6];
  const float* b1  = (const float*)d_in[7];
  const float* w2  = (const float*)d_in[8];
  const float* as2 = (const float*)d_in[9];
  const float* ad2 = (const float*)d_in[10];
  const float* b2  = (const float*)d_in[11];
  float* out = (float*)d_out;
  int wk = (out_size >= 2 * N * N) ? 1 : 0;

  cudaEventRecord(g_hs.e0, 0);
  cudaStreamWaitEvent(g_hs.s1, g_hs.e0, 0);
  cudaStreamWaitEvent(g_hs.s2, g_hs.e0, 0);
  cudaStreamWaitEvent(g_hs.s3, g_hs.e0, 0);

  // s3: zero out + g_B; later kMb
  kZero<<<512, 256, 0, g_hs.s3>>>(out, out_size);
  cudaEventRecord(g_hs.e3, g_hs.s3);

  // s1: vec1 -> sada
  kVec1<<<HD + N, 256, 0, g_hs.s1>>>(W1, a1, a2, b1, w2, xo);
  kSada<<<192, 256, 0, g_hs.s1>>>(x);
  cudaEventRecord(g_hs.e1, g_hs.s1);

  // s2: U partials -> U reduce
  kUp<<<24 * ZU, 256, 0, g_hs.s2>>>(W1, w2, xo);
  kUred<<<(HD * N) / 256, 256, 0, g_hs.s2>>>();
  cudaEventRecord(g_hs.e2, g_hs.s2);

  // s0 (default): critical path
  kCount<<<E2 / 256, 256>>>(ei);
  kScan<<<1, 256>>>();
  cudaStreamWaitEvent(0, g_hs.e3, 0);   // g_B zeroed before fill's atomicOr
  kFill<<<E2 / 256, 256>>>(ei);
  cudaEventRecord(g_hs.eF, 0);

  // s3: 2-hop masks, parallel with xg + H2
  cudaStreamWaitEvent(g_hs.s3, g_hs.eF, 0);
  kMb<<<N, 256, 0, g_hs.s3>>>();
  cudaEventRecord(g_hs.e4, g_hs.s3);

  cudaStreamWaitEvent(0, g_hs.e1, 0);   // sada done before xg
  kXg<<<N, 128>>>(x);
  cudaStreamWaitEvent(0, g_hs.e2, 0);   // U ready before H2
  kH2<<<576, 256>>>();
  cudaStreamWaitEvent(0, g_hs.e4, 0);   // masks ready before kF
  kF<<<N, 256>>>(as2, ad2, b2, out, wk);
}

// round 10
// speedup vs baseline: 1.2530x; 1.2530x over previous
#include <cuda_runtime.h>
#include <math.h>

#define N 1536
#define EE 24576
#define E2 (EE + N)
#define HD 128
#define DD 1280
#define NW 48   // N/32 bitmask words per row
#define ZU 20   // split-K depth for U

// ---------------- device scratch (no allocations allowed) ----------------
// Invariants across runs: g_cntT/g_cntS zero at entry (re-zeroed in kFill);
// g_B zeroed by kZero (event-ordered before kFill).
__device__ float g_wa[HD], g_wb[HD], g_c2[N];
__device__ float g_sa[N], g_da[N];
__device__ float g_U[HD * N];
__device__ float g_Up[ZU * HD * N];
__device__ float g_xg[N * HD];
__device__ float g_H2[N * N];
__device__ float g_H2b[N * N];
__device__ int   g_cntT[N], g_offT[N + 1], g_curT[N];
__device__ int   g_cntS[N], g_offS[N + 1], g_curS[N];
__device__ int   g_srcT[E2];
__device__ int   g_tgtS[EE];
__device__ unsigned g_B[N * NW];

__device__ __forceinline__ float lrelu(float v) { return v > 0.f ? v : 0.2f * v; }
__device__ __forceinline__ unsigned fenc(float f) {
  unsigned u = __float_as_uint(f);
  return (u & 0x80000000u) ? ~u : (u | 0x80000000u);
}

__device__ __forceinline__ float blockSum256(float v, float* sh) {
  __syncthreads();
  #pragma unroll
  for (int o = 16; o; o >>= 1) v += __shfl_xor_sync(0xFFFFFFFFu, v, o);
  if ((threadIdx.x & 31) == 0) sh[threadIdx.x >> 5] = v;
  __syncthreads();
  if (threadIdx.x < 32) {
    v = (threadIdx.x < 8) ? sh[threadIdx.x] : 0.f;
    #pragma unroll
    for (int o = 4; o; o >>= 1) v += __shfl_xor_sync(0xFFFFFFFFu, v, o);
  }
  return v;
}

// ---------- host-side fork/join resources ----------
struct HxStreams {
  cudaStream_t s1, s2, s3;
  cudaEvent_t e0, e1, e2, e3;
  HxStreams() {
    cudaStreamCreateWithFlags(&s1, cudaStreamNonBlocking);
    cudaStreamCreateWithFlags(&s2, cudaStreamNonBlocking);
    cudaStreamCreateWithFlags(&s3, cudaStreamNonBlocking);
    cudaEventCreateWithFlags(&e0, cudaEventDisableTiming);
    cudaEventCreateWithFlags(&e1, cudaEventDisableTiming);
    cudaEventCreateWithFlags(&e2, cudaEventDisableTiming);
    cudaEventCreateWithFlags(&e3, cudaEventDisableTiming);
  }
};
static HxStreams g_hs;

// ============ kZero: zero out buffer + g_B ===============
__global__ void kZero(float* __restrict__ out, int out_size) {
  int i = blockIdx.x * blockDim.x + threadIdx.x;
  int stride = gridDim.x * blockDim.x;
  for (int p = i; p < out_size; p += stride) out[p] = 0.f;
  for (int p = i; p < N * NW; p += stride) g_B[p] = 0u;
}

// ============ kCount ===================================
__global__ void kCount(const int* __restrict__ ei) {
  int idx = blockIdx.x * blockDim.x + threadIdx.x;
  if (idx < EE) {
    atomicAdd(&g_cntS[ei[idx]], 1);
    atomicAdd(&g_cntT[ei[EE + idx]], 1);
  } else if (idx < E2) {
    atomicAdd(&g_cntT[idx - EE], 1);
  }
}

// ============ kScan ========================
__global__ void kScan() {
  __shared__ int part[256];
  int tid = threadIdx.x;
  int base = tid * 6;
  {
    int a[6]; int s = 0;
    #pragma unroll
    for (int u = 0; u < 6; u++) { a[u] = g_cntT[base + u]; s += a[u]; }
    part[tid] = s;
    __syncthreads();
    for (int o = 1; o < 256; o <<= 1) {
      int v = (tid >= o) ? part[tid - o] : 0;
      __syncthreads();
      part[tid] += v;
      __syncthreads();
    }
    int excl = part[tid] - s;
    #pragma unroll
    for (int u = 0; u < 6; u++) {
      g_offT[base + u] = excl; g_curT[base + u] = excl; excl += a[u];
    }
    if (tid == 255) g_offT[N] = part[255];
    __syncthreads();
  }
  {
    int a[6]; int s = 0;
    #pragma unroll
    for (int u = 0; u < 6; u++) { a[u] = g_cntS[base + u]; s += a[u]; }
    part[tid] = s;
    __syncthreads();
    for (int o = 1; o < 256; o <<= 1) {
      int v = (tid >= o) ? part[tid - o] : 0;
      __syncthreads();
      part[tid] += v;
      __syncthreads();
    }
    int excl = part[tid] - s;
    #pragma unroll
    for (int u = 0; u < 6; u++) {
      g_offS[base + u] = excl; g_curS[base + u] = excl; excl += a[u];
    }
    if (tid == 255) g_offS[N] = part[255];
  }
}

// ============ kFill: CSR fill + B build + cnt re-zero ======================
__global__ void kFill(const int* __restrict__ ei) {
  int idx = blockIdx.x * blockDim.x + threadIdx.x;
  if (idx < N) { g_cntT[idx] = 0; g_cntS[idx] = 0; }
  if (idx >= E2) return;
  int s, t;
  if (idx < EE) { s = ei[idx]; t = ei[EE + idx]; }
  else { s = t = idx - EE; }
  int pos = atomicAdd(&g_curT[t], 1);
  g_srcT[pos] = s;
  if (idx < EE) {
    int ps = atomicAdd(&g_curS[s], 1);
    g_tgtS[ps] = t;
    atomicOr(&g_B[t * NW + (s >> 5)], 1u << (s & 31));
  }
}

// ============ kVec1 ============================
__global__ __launch_bounds__(256) void kVec1(const float* __restrict__ W1,
                                             const float* __restrict__ a1,
                                             const float* __restrict__ a2,
                                             const float* __restrict__ b1,
                                             const float* __restrict__ w2,
                                             const float* __restrict__ xo) {
  __shared__ float sh[8];
  int b = blockIdx.x, tid = threadIdx.x;
  if (b < HD) {
    float s1 = 0.f, s2 = 0.f;
    for (int d = tid; d < DD; d += 256) {
      float w = W1[b * DD + d];
      s1 += w * a1[d]; s2 += w * a2[d];
    }
    float r1 = blockSum256(s1, sh);
    float r2 = blockSum256(s2, sh);
    if (tid == 0) { g_wa[b] = r1; g_wb[b] = r2; }
  } else {
    int j = b - HD;
    float s = 0.f;
    for (int d = tid; d < DD; d += 256) s += b1[d] * w2[d] * xo[j * DD + d];
    float r = blockSum256(s, sh);
    if (tid == 0) g_c2[j] = r;
  }
}

// ============ kSada ==================================
__global__ __launch_bounds__(256) void kSada(const float* __restrict__ x) {
  int node = blockIdx.x * 8 + (threadIdx.x >> 5);
  int lane = threadIdx.x & 31;
  if (node >= N) return;
  float s1 = 0.f, s2 = 0.f;
  #pragma unroll
  for (int k = lane; k < HD; k += 32) {
    float xv = x[node * HD + k];
    s1 += xv * g_wa[k]; s2 += xv * g_wb[k];
  }
  #pragma unroll
  for (int o = 16; o; o >>= 1) {
    s1 += __shfl_xor_sync(0xFFFFFFFFu, s1, o);
    s2 += __shfl_xor_sync(0xFFFFFFFFu, s2, o);
  }
  if (lane == 0) { g_sa[node] = s1; g_da[node] = s2; }
}

// ============ kUp: U split-K partials ====================
__global__ __launch_bounds__(256, 2) void kUp(const float* __restrict__ W1,
                                              const float* __restrict__ w2,
                                              const float* __restrict__ xo) {
  __shared__ float As[2][16][65];
  __shared__ float Bs[2][16][129];
  int b = blockIdx.x;
  int tileid = b % 24;
  int z = b / 24;
  int j0 = (tileid % 12) * 128;
  int m0 = (tileid / 12) * 64;
  int k0 = z * 64;
  int tid = threadIdx.x, tx = tid & 15, ty = tid >> 4;
  float acc[4][8];
  #pragma unroll
  for (int u = 0; u < 4; u++)
    #pragma unroll
    for (int w = 0; w < 8; w++) acc[u][w] = 0.f;
  auto load = [&](int buf, int kc) {
    #pragma unroll
    for (int l = tid; l < 64 * 16; l += 256) {
      int k = l & 15, m = l >> 4;
      As[buf][k][m] = W1[(m0 + m) * DD + k0 + kc + k] * w2[k0 + kc + k];
    }
    #pragma unroll
    for (int l = tid; l < 128 * 16; l += 256) {
      int k = l & 15, j = l >> 4;
      Bs[buf][k][j] = xo[(j0 + j) * DD + k0 + kc + k];
    }
  };
  load(0, 0);
  __syncthreads();
  for (int c = 0; c < 4; c++) {
    int buf = c & 1;
    if (c < 3) load(buf ^ 1, (c + 1) * 16);
    #pragma unroll
    for (int kk = 0; kk < 16; kk++) {
      float ra[4], rb[8];
      #pragma unroll
      for (int u = 0; u < 4; u++) ra[u] = As[buf][kk][u * 16 + ty];
      #pragma unroll
      for (int w = 0; w < 8; w++) rb[w] = Bs[buf][kk][w * 16 + tx];
      #pragma unroll
      for (int u = 0; u < 4; u++)
        #pragma unroll
        for (int w = 0; w < 8; w++) acc[u][w] += ra[u] * rb[w];
    }
    __syncthreads();
  }
  float* Up = g_Up + z * (HD * N);
  #pragma unroll
  for (int u = 0; u < 4; u++)
    #pragma unroll
    for (int w = 0; w < 8; w++)
      Up[(m0 + u * 16 + ty) * N + j0 + w * 16 + tx] = acc[u][w];
}

// ============ kUred ===============================
__global__ void kUred() {
  int idx = blockIdx.x * blockDim.x + threadIdx.x;
  float s = 0.f;
  #pragma unroll
  for (int z = 0; z < ZU; z++) s += g_Up[z * (HD * N) + idx];
  g_U[idx] = s;
}

// ============ kXg: fused GAT-1 softmax + xg = P@x ==========================
__global__ __launch_bounds__(128) void kXg(const float* __restrict__ x) {
  int t = blockIdx.x, tid = threadIdx.x;
  __shared__ int   ss[256];
  __shared__ float sw[256];
  __shared__ float sh[4];
  int p0 = g_offT[t], p1 = g_offT[t + 1];
  float dt = g_da[t];
  float m = -3.4e38f;
  for (int p = p0 + tid; p < p1; p += 128)
    m = fmaxf(m, lrelu(g_sa[g_srcT[p]] + dt));
  #pragma unroll
  for (int o = 16; o; o >>= 1) m = fmaxf(m, __shfl_xor_sync(0xFFFFFFFFu, m, o));
  if ((tid & 31) == 0) sh[tid >> 5] = m;
  __syncthreads();
  m = fmaxf(fmaxf(sh[0], sh[1]), fmaxf(sh[2], sh[3]));
  float acc = 0.f, dsum = 0.f;
  for (int base = p0; base < p1; base += 256) {
    int nc = min(256, p1 - base);
    for (int q = tid; q < nc; q += 128) {
      int s = g_srcT[base + q];
      float w = expf(lrelu(g_sa[s] + dt) - m);
      ss[q] = s;
      sw[q] = w;
      dsum += w;
    }
    __syncthreads();
    for (int q = 0; q < nc; q++)
      acc += sw[q] * x[ss[q] * HD + tid];
    __syncthreads();
  }
  float den = dsum;
  #pragma unroll
  for (int o = 16; o; o >>= 1) den += __shfl_xor_sync(0xFFFFFFFFu, den, o);
  if ((tid & 31) == 0) sh[tid >> 5] = den;
  __syncthreads();
  den = sh[0] + sh[1] + sh[2] + sh[3];
  g_xg[t * HD + tid] = acc / den;
}

// ============ kH2: H2 partials = xg @ U (split-K=2) ==========
__global__ __launch_bounds__(256, 2) void kH2() {
  __shared__ float As[2][16][65];
  __shared__ float Bs[2][16][129];
  int b = blockIdx.x;
  int tile = b % 288;
  int z = b / 288;
  int j0 = (tile % 12) * 128;
  int m0 = (tile / 12) * 64;
  int k0 = z * 64;
  int tid = threadIdx.x, tx = tid & 15, ty = tid >> 4;
  float acc[4][8];
  #pragma unroll
  for (int u = 0; u < 4; u++)
    #pragma unroll
    for (int w = 0; w < 8; w++) acc[u][w] = 0.f;
  auto load = [&](int buf, int kc) {
    #pragma unroll
    for (int l = tid; l < 64 * 16; l += 256) {
      int k = l & 15, m = l >> 4;
      As[buf][k][m] = g_xg[(m0 + m) * HD + k0 + kc + k];
    }
    #pragma unroll
    for (int l = tid; l < 16 * 128; l += 256) {
      int j = l & 127, k = l >> 7;
      Bs[buf][k][j] = g_U[(k0 + kc + k) * N + j0 + j];
    }
  };
  load(0, 0);
  __syncthreads();
  for (int c = 0; c < 4; c++) {
    int buf = c & 1;
    if (c < 3) load(buf ^ 1, (c + 1) * 16);
    #pragma unroll
    for (int kk = 0; kk < 16; kk++) {
      float ra[4], rb[8];
      #pragma unroll
      for (int u = 0; u < 4; u++) ra[u] = As[buf][kk][u * 16 + ty];
      #pragma unroll
      for (int w = 0; w < 8; w++) rb[w] = Bs[buf][kk][w * 16 + tx];
      #pragma unroll
      for (int u = 0; u < 4; u++)
        #pragma unroll
        for (int w = 0; w < 8; w++) acc[u][w] += ra[u] * rb[w];
    }
    __syncthreads();
  }
  float* outp = z ? g_H2b : g_H2;
  #pragma unroll
  for (int u = 0; u < 4; u++)
    #pragma unroll
    for (int w = 0; w < 8; w++)
      outp[(m0 + u * 16 + ty) * N + j0 + w * 16 + tx] = acc[u][w];
}

// == kF: per-row 2-hop mask + single-pass online gather softmax + select ====
__global__ __launch_bounds__(256) void kF(const float* __restrict__ pas2,
                                          const float* __restrict__ pad2,
                                          const float* __restrict__ pb2,
                                          float* __restrict__ out, int wk) {
  int i = blockIdx.x, tid = threadIdx.x;
  __shared__ float v[N];
  __shared__ int vlist[N];
  __shared__ float scl[N];
  __shared__ unsigned k32[N];
  __shared__ unsigned mb[NW];
  __shared__ int wcnt[NW + 1];
  __shared__ int hist[256];
  __shared__ unsigned s_pfx;
  __shared__ int s_rem;

  float as2 = pas2[0], ad2 = pad2[0], b2 = pb2[0];

  if (tid < NW) {
    unsigned w = g_B[i * NW + tid];
    if (tid == (i >> 5)) w |= 1u << (i & 31);
    mb[tid] = w;
  }
  for (int j = tid; j < N; j += 256)
    v[j] = g_H2[i * N + j] + g_H2b[i * N + j] + g_c2[j];
  __syncthreads();
  // 1-hop list
  if (tid < NW) wcnt[tid] = __popc(mb[tid]);
  __syncthreads();
  if (tid == 0) {
    int s = 0;
    for (int w = 0; w < NW; w++) { int c = wcnt[w]; wcnt[w] = s; s += c; }
    wcnt[NW] = s;
  }
  __syncthreads();
  int nk = wcnt[NW];
  if (tid < NW) {
    unsigned b = mb[tid]; int o = wcnt[tid];
    while (b) { int t = __ffs(b) - 1; b &= b - 1; vlist[o++] = tid * 32 + t; }
  }
  __syncthreads();
  // 2-hop
  if (tid < 4 * NW) {
    int sy = tid / NW, cx = tid % NW;
    unsigned acc = 0u;
    for (int q = sy; q < nk; q += 4) acc |= g_B[vlist[q] * NW + cx];
    atomicOr(&mb[cx], acc);
  }
  __syncthreads();
  // valid list (ascending index order — stable tie-break depends on it)
  if (tid < NW) wcnt[tid] = __popc(mb[tid]);
  __syncthreads();
  if (tid == 0) {
    int s = 0;
    for (int w = 0; w < NW; w++) { int c = wcnt[w]; wcnt[w] = s; s += c; }
    wcnt[NW] = s;
  }
  __syncthreads();
  int nvv = wcnt[NW];
  if (tid < NW) {
    unsigned b = mb[tid]; int o = wcnt[tid];
    while (b) { int t = __ffs(b) - 1; b &= b - 1; vlist[o++] = tid * 32 + t; }
  }
  __syncthreads();
  // single-pass ONLINE gather softmax: thread per valid target, registers only
  for (int li = tid; li < nvv; li += 256) {
    int t = vlist[li];
    int p0 = g_offT[t], p1 = g_offT[t + 1];
    float adt = ad2 * v[t];
    float m = -3.4e38f, den = 0.f, num = 0.f;
    for (int p = p0; p < p1; p++) {
      int s = g_srcT[p];
      if ((mb[s >> 5] >> (s & 31)) & 1u) {
        float vs = v[s];
        float e = lrelu(fmaf(as2, vs, adt));
        if (e <= m) {
          float w = expf(e - m);
          den += w;
          num += w * vs;
        } else {
          float r = expf(m - e);   // 0 on first valid edge (m = -3.4e38)
          den = fmaf(den, r, 1.f);
          num = fmaf(num, r, vs);
          m = e;
        }
      }
    }
    float sc = num / fmaxf(den, 1e-12f) + b2;
    scl[li] = sc;
    k32[li] = fenc(sc);
  }
  int kk = (nvv + 1) >> 1;
  if (tid == 0) { s_rem = kk; s_pfx = 0u; }
  __syncthreads();
  // radix-select the kk-th largest key (4 rounds of 8 bits)
  for (int r = 0; r < 4; r++) {
    int shift = 24 - 8 * r;
    hist[tid] = 0;
    __syncthreads();
    unsigned pfx = s_pfx;
    for (int li = tid; li < nvv; li += 256) {
      unsigned key = k32[li];
      bool cand = (r == 0) || ((key >> (shift + 8)) == pfx);
      if (cand) atomicAdd(&hist[(key >> shift) & 255], 1);
    }
    __syncthreads();
    if (tid < 32) {
      int s = 0;
      #pragma unroll
      for (int u = 0; u < 8; u++) s += hist[tid * 8 + u];
      int cum = s;
      #pragma unroll
      for (int o = 1; o < 32; o <<= 1) {
        int t2 = __shfl_down_sync(0xFFFFFFFFu, cum, o);
        if (tid + o < 32) cum += t2;
      }
      int run = cum - s;
      int rem = s_rem;
      unsigned pfxold = s_pfx;
      int fb = -1, frem = 0;
      for (int bb = tid * 8 + 7; bb >= tid * 8; bb--) {
        int h = hist[bb];
        if (run < rem && rem <= run + h) { fb = bb; frem = rem - run; }
        run += h;
      }
      __syncwarp();
      if (fb >= 0) { s_pfx = (pfxold << 8) | (unsigned)fb; s_rem = frem; }
    }
    __syncthreads();
  }
  unsigned T = s_pfx;
  int rem = s_rem;
  // keep: key > T, or key == T with tie-rank (ascending index) < rem
  for (int li = tid; li < nvv; li += 256) {
    unsigned key = k32[li];
    bool keep = key > T;
    if (!keep && key == T) {
      int cnt = 0;
      for (int l2 = 0; l2 < li; l2++) cnt += (k32[l2] == T);
      keep = cnt < rem;
    }
    if (keep) {
      int j = vlist[li];
      float sj = scl[li];
      out[i * N + j] = 1.f / (1.f + expf(-sj));
      if (wk) out[N * N + i * N + j] = 1.f;
    }
  }
}

// ---------------- launch: forked-capture graph ----------------
extern "C" void kernel_launch(void* const* d_in, const int* in_sizes, int n_in,
                              void* d_out, int out_size) {
  const float* x   = (const float*)d_in[0];
  const float* xo  = (const float*)d_in[1];
  const int*   ei  = (const int*)d_in[2];
  const float* W1  = (const float*)d_in[4];
  const float* a1  = (const float*)d_in[5];
  const float* a2  = (const float*)d_in[6];
  const float* b1  = (const float*)d_in[7];
  const float* w2  = (const float*)d_in[8];
  const float* as2 = (const float*)d_in[9];
  const float* ad2 = (const float*)d_in[10];
  const float* b2  = (const float*)d_in[11];
  float* out = (float*)d_out;
  int wk = (out_size >= 2 * N * N) ? 1 : 0;

  cudaEventRecord(g_hs.e0, 0);
  cudaStreamWaitEvent(g_hs.s1, g_hs.e0, 0);
  cudaStreamWaitEvent(g_hs.s2, g_hs.e0, 0);
  cudaStreamWaitEvent(g_hs.s3, g_hs.e0, 0);

  // s3: zero out + g_B
  kZero<<<512, 256, 0, g_hs.s3>>>(out, out_size);
  cudaEventRecord(g_hs.e3, g_hs.s3);

  // s1: vec1 -> sada
  kVec1<<<HD + N, 256, 0, g_hs.s1>>>(W1, a1, a2, b1, w2, xo);
  kSada<<<192, 256, 0, g_hs.s1>>>(x);
  cudaEventRecord(g_hs.e1, g_hs.s1);

  // s2: U partials -> U reduce
  kUp<<<24 * ZU, 256, 0, g_hs.s2>>>(W1, w2, xo);
  kUred<<<(HD * N) / 256, 256, 0, g_hs.s2>>>();
  cudaEventRecord(g_hs.e2, g_hs.s2);

  // s0 (default): critical path
  kCount<<<E2 / 256, 256>>>(ei);
  kScan<<<1, 256>>>();
  cudaStreamWaitEvent(0, g_hs.e3, 0);   // g_B zeroed before fill's atomicOr
  kFill<<<E2 / 256, 256>>>(ei);
  cudaStreamWaitEvent(0, g_hs.e1, 0);   // sada done before xg
  kXg<<<N, 128>>>(x);
  cudaStreamWaitEvent(0, g_hs.e2, 0);   // U ready before H2
  kH2<<<576, 256>>>();
  kF<<<N, 256>>>(as2, ad2, b2, out, wk);
}

// round 11
// speedup vs baseline: 1.4166x; 1.1306x over previous
#include <cuda_runtime.h>
#include <math.h>

#define N 1536
#define EE 24576
#define E2 (EE + N)
#define HD 128
#define DD 1280
#define NW 48   // N/32 bitmask words per row
#define ZU 10   // split-K depth for U (K-chunk 128)

// ---------------- device scratch (no allocations allowed) ----------------
// Invariants across runs: g_cntT/g_cntS zero at entry (re-zeroed in kFill);
// g_B zeroed by kZero (event-ordered before kFill).
__device__ float g_wa[HD], g_wb[HD], g_c2[N];
__device__ float g_sa[N], g_da[N];
__device__ float g_U[HD * N];
__device__ float g_Up[ZU * HD * N];
__device__ float g_xg[N * HD];
__device__ float g_H2[N * N];
__device__ float g_H2b[N * N];
__device__ int   g_cntT[N], g_offT[N + 1], g_curT[N];
__device__ int   g_cntS[N], g_offS[N + 1], g_curS[N];
__device__ int   g_srcT[E2];
__device__ int   g_tgtS[EE];
__device__ unsigned g_B[N * NW];

__device__ __forceinline__ float lrelu(float v) { return v > 0.f ? v : 0.2f * v; }
__device__ __forceinline__ unsigned fenc(float f) {
  unsigned u = __float_as_uint(f);
  return (u & 0x80000000u) ? ~u : (u | 0x80000000u);
}

__device__ __forceinline__ float blockSum256(float v, float* sh) {
  __syncthreads();
  #pragma unroll
  for (int o = 16; o; o >>= 1) v += __shfl_xor_sync(0xFFFFFFFFu, v, o);
  if ((threadIdx.x & 31) == 0) sh[threadIdx.x >> 5] = v;
  __syncthreads();
  if (threadIdx.x < 32) {
    v = (threadIdx.x < 8) ? sh[threadIdx.x] : 0.f;
    #pragma unroll
    for (int o = 4; o; o >>= 1) v += __shfl_xor_sync(0xFFFFFFFFu, v, o);
  }
  return v;
}

// ---------- host-side fork/join resources ----------
struct HxStreams {
  cudaStream_t s1, s2, s3;
  cudaEvent_t e0, e1, e2, e3;
  HxStreams() {
    cudaStreamCreateWithFlags(&s1, cudaStreamNonBlocking);
    cudaStreamCreateWithFlags(&s2, cudaStreamNonBlocking);
    cudaStreamCreateWithFlags(&s3, cudaStreamNonBlocking);
    cudaEventCreateWithFlags(&e0, cudaEventDisableTiming);
    cudaEventCreateWithFlags(&e1, cudaEventDisableTiming);
    cudaEventCreateWithFlags(&e2, cudaEventDisableTiming);
    cudaEventCreateWithFlags(&e3, cudaEventDisableTiming);
  }
};
static HxStreams g_hs;

// ============ kZero: zero out buffer + g_B ===============
__global__ void kZero(float* __restrict__ out, int out_size) {
  int i = blockIdx.x * blockDim.x + threadIdx.x;
  int stride = gridDim.x * blockDim.x;
  for (int p = i; p < out_size; p += stride) out[p] = 0.f;
  for (int p = i; p < N * NW; p += stride) g_B[p] = 0u;
}

// ============ kCount ===================================
__global__ void kCount(const int* __restrict__ ei) {
  int idx = blockIdx.x * blockDim.x + threadIdx.x;
  if (idx < EE) {
    atomicAdd(&g_cntS[ei[idx]], 1);
    atomicAdd(&g_cntT[ei[EE + idx]], 1);
  } else if (idx < E2) {
    atomicAdd(&g_cntT[idx - EE], 1);
  }
}

// ============ kScan ========================
__global__ void kScan() {
  __shared__ int part[256];
  int tid = threadIdx.x;
  int base = tid * 6;
  {
    int a[6]; int s = 0;
    #pragma unroll
    for (int u = 0; u < 6; u++) { a[u] = g_cntT[base + u]; s += a[u]; }
    part[tid] = s;
    __syncthreads();
    for (int o = 1; o < 256; o <<= 1) {
      int v = (tid >= o) ? part[tid - o] : 0;
      __syncthreads();
      part[tid] += v;
      __syncthreads();
    }
    int excl = part[tid] - s;
    #pragma unroll
    for (int u = 0; u < 6; u++) {
      g_offT[base + u] = excl; g_curT[base + u] = excl; excl += a[u];
    }
    if (tid == 255) g_offT[N] = part[255];
    __syncthreads();
  }
  {
    int a[6]; int s = 0;
    #pragma unroll
    for (int u = 0; u < 6; u++) { a[u] = g_cntS[base + u]; s += a[u]; }
    part[tid] = s;
    __syncthreads();
    for (int o = 1; o < 256; o <<= 1) {
      int v = (tid >= o) ? part[tid - o] : 0;
      __syncthreads();
      part[tid] += v;
      __syncthreads();
    }
    int excl = part[tid] - s;
    #pragma unroll
    for (int u = 0; u < 6; u++) {
      g_offS[base + u] = excl; g_curS[base + u] = excl; excl += a[u];
    }
    if (tid == 255) g_offS[N] = part[255];
  }
}

// ============ kFill: CSR fill + B build + cnt re-zero ======================
__global__ void kFill(const int* __restrict__ ei) {
  int idx = blockIdx.x * blockDim.x + threadIdx.x;
  if (idx < N) { g_cntT[idx] = 0; g_cntS[idx] = 0; }
  if (idx >= E2) return;
  int s, t;
  if (idx < EE) { s = ei[idx]; t = ei[EE + idx]; }
  else { s = t = idx - EE; }
  int pos = atomicAdd(&g_curT[t], 1);
  g_srcT[pos] = s;
  if (idx < EE) {
    int ps = atomicAdd(&g_curS[s], 1);
    g_tgtS[ps] = t;
    atomicOr(&g_B[t * NW + (s >> 5)], 1u << (s & 31));
  }
}

// ============ kVec1 ============================
__global__ __launch_bounds__(256) void kVec1(const float* __restrict__ W1,
                                             const float* __restrict__ a1,
                                             const float* __restrict__ a2,
                                             const float* __restrict__ b1,
                                             const float* __restrict__ w2,
                                             const float* __restrict__ xo) {
  __shared__ float sh[8];
  int b = blockIdx.x, tid = threadIdx.x;
  if (b < HD) {
    float s1 = 0.f, s2 = 0.f;
    for (int d = tid; d < DD; d += 256) {
      float w = W1[b * DD + d];
      s1 += w * a1[d]; s2 += w * a2[d];
    }
    float r1 = blockSum256(s1, sh);
    float r2 = blockSum256(s2, sh);
    if (tid == 0) { g_wa[b] = r1; g_wb[b] = r2; }
  } else {
    int j = b - HD;
    float s = 0.f;
    for (int d = tid; d < DD; d += 256) s += b1[d] * w2[d] * xo[j * DD + d];
    float r = blockSum256(s, sh);
    if (tid == 0) g_c2[j] = r;
  }
}

// ============ kSada ==================================
__global__ __launch_bounds__(256) void kSada(const float* __restrict__ x) {
  int node = blockIdx.x * 8 + (threadIdx.x >> 5);
  int lane = threadIdx.x & 31;
  if (node >= N) return;
  float s1 = 0.f, s2 = 0.f;
  #pragma unroll
  for (int k = lane; k < HD; k += 32) {
    float xv = x[node * HD + k];
    s1 += xv * g_wa[k]; s2 += xv * g_wb[k];
  }
  #pragma unroll
  for (int o = 16; o; o >>= 1) {
    s1 += __shfl_xor_sync(0xFFFFFFFFu, s1, o);
    s2 += __shfl_xor_sync(0xFFFFFFFFu, s2, o);
  }
  if (lane == 0) { g_sa[node] = s1; g_da[node] = s2; }
}

// ==== kUp: U split-K partials; float4 fragments, LDS.128 inner loop ========
__global__ __launch_bounds__(256, 2) void kUp(const float* __restrict__ W1,
                                              const float* __restrict__ w2,
                                              const float* __restrict__ xo) {
  __shared__ __align__(16) float As[2][16][68];    // 64 cols + 4 pad (16B-aligned rows)
  __shared__ __align__(16) float Bs[2][16][132];   // 128 cols + 4 pad
  int b = blockIdx.x;
  int tileid = b % 24;
  int z = b / 24;
  int j0 = (tileid % 12) * 128;
  int m0 = (tileid / 12) * 64;
  int k0 = z * 128;
  int tid = threadIdx.x, tx = tid & 15, ty = tid >> 4;
  float acc[4][8];
  #pragma unroll
  for (int u = 0; u < 4; u++)
    #pragma unroll
    for (int w = 0; w < 8; w++) acc[u][w] = 0.f;
  auto load = [&](int buf, int kc) {
    #pragma unroll
    for (int l = tid; l < 64 * 16; l += 256) {
      int k = l & 15, m = l >> 4;
      As[buf][k][m] = W1[(m0 + m) * DD + k0 + kc + k] * w2[k0 + kc + k];
    }
    #pragma unroll
    for (int l = tid; l < 128 * 16; l += 256) {
      int k = l & 15, j = l >> 4;
      Bs[buf][k][j] = xo[(j0 + j) * DD + k0 + kc + k];
    }
  };
  load(0, 0);
  __syncthreads();
  for (int c = 0; c < 8; c++) {
    int buf = c & 1;
    if (c < 7) load(buf ^ 1, (c + 1) * 16);
    #pragma unroll
    for (int kk = 0; kk < 16; kk++) {
      float4 ra  = *(const float4*)&As[buf][kk][ty * 4];
      float4 rb0 = *(const float4*)&Bs[buf][kk][tx * 4];
      float4 rb1 = *(const float4*)&Bs[buf][kk][64 + tx * 4];
      float rav[4] = {ra.x, ra.y, ra.z, ra.w};
      float rbv[8] = {rb0.x, rb0.y, rb0.z, rb0.w, rb1.x, rb1.y, rb1.z, rb1.w};
      #pragma unroll
      for (int u = 0; u < 4; u++)
        #pragma unroll
        for (int w = 0; w < 8; w++) acc[u][w] = fmaf(rav[u], rbv[w], acc[u][w]);
    }
    __syncthreads();
  }
  float* Up = g_Up + z * (HD * N);
  #pragma unroll
  for (int u = 0; u < 4; u++) {
    int row = m0 + ty * 4 + u;
    *(float4*)&Up[row * N + j0 + tx * 4] =
        make_float4(acc[u][0], acc[u][1], acc[u][2], acc[u][3]);
    *(float4*)&Up[row * N + j0 + 64 + tx * 4] =
        make_float4(acc[u][4], acc[u][5], acc[u][6], acc[u][7]);
  }
}

// ============ kUred ===============================
__global__ void kUred() {
  int idx = blockIdx.x * blockDim.x + threadIdx.x;
  float s = 0.f;
  #pragma unroll
  for (int z = 0; z < ZU; z++) s += g_Up[z * (HD * N) + idx];
  g_U[idx] = s;
}

// ============ kXg: fused GAT-1 softmax + xg = P@x ==========================
__global__ __launch_bounds__(128) void kXg(const float* __restrict__ x) {
  int t = blockIdx.x, tid = threadIdx.x;
  __shared__ int   ss[256];
  __shared__ float sw[256];
  __shared__ float sh[4];
  int p0 = g_offT[t], p1 = g_offT[t + 1];
  float dt = g_da[t];
  float m = -3.4e38f;
  for (int p = p0 + tid; p < p1; p += 128)
    m = fmaxf(m, lrelu(g_sa[g_srcT[p]] + dt));
  #pragma unroll
  for (int o = 16; o; o >>= 1) m = fmaxf(m, __shfl_xor_sync(0xFFFFFFFFu, m, o));
  if ((tid & 31) == 0) sh[tid >> 5] = m;
  __syncthreads();
  m = fmaxf(fmaxf(sh[0], sh[1]), fmaxf(sh[2], sh[3]));
  float acc = 0.f, dsum = 0.f;
  for (int base = p0; base < p1; base += 256) {
    int nc = min(256, p1 - base);
    for (int q = tid; q < nc; q += 128) {
      int s = g_srcT[base + q];
      float w = expf(lrelu(g_sa[s] + dt) - m);
      ss[q] = s;
      sw[q] = w;
      dsum += w;
    }
    __syncthreads();
    for (int q = 0; q < nc; q++)
      acc += sw[q] * x[ss[q] * HD + tid];
    __syncthreads();
  }
  float den = dsum;
  #pragma unroll
  for (int o = 16; o; o >>= 1) den += __shfl_xor_sync(0xFFFFFFFFu, den, o);
  if ((tid & 31) == 0) sh[tid >> 5] = den;
  __syncthreads();
  den = sh[0] + sh[1] + sh[2] + sh[3];
  g_xg[t * HD + tid] = acc / den;
}

// ==== kH2: H2 partials = xg @ U; float4 fragments, LDS.128 inner loop ======
__global__ __launch_bounds__(256, 2) void kH2() {
  __shared__ __align__(16) float As[2][16][68];
  __shared__ __align__(16) float Bs[2][16][132];
  int b = blockIdx.x;
  int tile = b % 288;
  int z = b / 288;
  int j0 = (tile % 12) * 128;
  int m0 = (tile / 12) * 64;
  int k0 = z * 64;
  int tid = threadIdx.x, tx = tid & 15, ty = tid >> 4;
  float acc[4][8];
  #pragma unroll
  for (int u = 0; u < 4; u++)
    #pragma unroll
    for (int w = 0; w < 8; w++) acc[u][w] = 0.f;
  auto load = [&](int buf, int kc) {
    #pragma unroll
    for (int l = tid; l < 64 * 16; l += 256) {
      int k = l & 15, m = l >> 4;
      As[buf][k][m] = g_xg[(m0 + m) * HD + k0 + kc + k];
    }
    #pragma unroll
    for (int l = tid; l < 16 * 128; l += 256) {
      int j = l & 127, k = l >> 7;
      Bs[buf][k][j] = g_U[(k0 + kc + k) * N + j0 + j];
    }
  };
  load(0, 0);
  __syncthreads();
  for (int c = 0; c < 4; c++) {
    int buf = c & 1;
    if (c < 3) load(buf ^ 1, (c + 1) * 16);
    #pragma unroll
    for (int kk = 0; kk < 16; kk++) {
      float4 ra  = *(const float4*)&As[buf][kk][ty * 4];
      float4 rb0 = *(const float4*)&Bs[buf][kk][tx * 4];
      float4 rb1 = *(const float4*)&Bs[buf][kk][64 + tx * 4];
      float rav[4] = {ra.x, ra.y, ra.z, ra.w};
      float rbv[8] = {rb0.x, rb0.y, rb0.z, rb0.w, rb1.x, rb1.y, rb1.z, rb1.w};
      #pragma unroll
      for (int u = 0; u < 4; u++)
        #pragma unroll
        for (int w = 0; w < 8; w++) acc[u][w] = fmaf(rav[u], rbv[w], acc[u][w]);
    }
    __syncthreads();
  }
  float* outp = z ? g_H2b : g_H2;
  #pragma unroll
  for (int u = 0; u < 4; u++) {
    int row = m0 + ty * 4 + u;
    *(float4*)&outp[row * N + j0 + tx * 4] =
        make_float4(acc[u][0], acc[u][1], acc[u][2], acc[u][3]);
    *(float4*)&outp[row * N + j0 + 64 + tx * 4] =
        make_float4(acc[u][4], acc[u][5], acc[u][6], acc[u][7]);
  }
}

// == kF: per-row 2-hop mask + two-pass gather softmax + radix-select ========
__global__ __launch_bounds__(256) void kF(const float* __restrict__ pas2,
                                          const float* __restrict__ pad2,
                                          const float* __restrict__ pb2,
                                          float* __restrict__ out, int wk) {
  int i = blockIdx.x, tid = threadIdx.x;
  __shared__ float v[N];
  __shared__ int vlist[N];
  __shared__ float scl[N];
  __shared__ unsigned k32[N];
  __shared__ unsigned mb[NW];
  __shared__ int wcnt[NW + 1];
  __shared__ int hist[256];
  __shared__ unsigned s_pfx;
  __shared__ int s_rem;

  float as2 = pas2[0], ad2 = pad2[0], b2 = pb2[0];

  if (tid < NW) {
    unsigned w = g_B[i * NW + tid];
    if (tid == (i >> 5)) w |= 1u << (i & 31);
    mb[tid] = w;
  }
  for (int j = tid; j < N; j += 256)
    v[j] = g_H2[i * N + j] + g_H2b[i * N + j] + g_c2[j];
  __syncthreads();
  // 1-hop list
  if (tid < NW) wcnt[tid] = __popc(mb[tid]);
  __syncthreads();
  if (tid == 0) {
    int s = 0;
    for (int w = 0; w < NW; w++) { int c = wcnt[w]; wcnt[w] = s; s += c; }
    wcnt[NW] = s;
  }
  __syncthreads();
  int nk = wcnt[NW];
  if (tid < NW) {
    unsigned b = mb[tid]; int o = wcnt[tid];
    while (b) { int t = __ffs(b) - 1; b &= b - 1; vlist[o++] = tid * 32 + t; }
  }
  __syncthreads();
  // 2-hop
  if (tid < 4 * NW) {
    int sy = tid / NW, cx = tid % NW;
    unsigned acc = 0u;
    for (int q = sy; q < nk; q += 4) acc |= g_B[vlist[q] * NW + cx];
    atomicOr(&mb[cx], acc);
  }
  __syncthreads();
  // valid list (ascending index order — stable tie-break depends on it)
  if (tid < NW) wcnt[tid] = __popc(mb[tid]);
  __syncthreads();
  if (tid == 0) {
    int s = 0;
    for (int w = 0; w < NW; w++) { int c = wcnt[w]; wcnt[w] = s; s += c; }
    wcnt[NW] = s;
  }
  __syncthreads();
  int nvv = wcnt[NW];
  if (tid < NW) {
    unsigned b = mb[tid]; int o = wcnt[tid];
    while (b) { int t = __ffs(b) - 1; b &= b - 1; vlist[o++] = tid * 32 + t; }
  }
  __syncthreads();
  // two-pass gather softmax: one thread per valid target, registers only
  for (int li = tid; li < nvv; li += 256) {
    int t = vlist[li];
    int p0 = g_offT[t], p1 = g_offT[t + 1];
    float adt = ad2 * v[t];
    float m = -3.4e38f;
    for (int p = p0; p < p1; p++) {
      int s = g_srcT[p];
      if ((mb[s >> 5] >> (s & 31)) & 1u)
        m = fmaxf(m, lrelu(fmaf(as2, v[s], adt)));
    }
    float den = 0.f, num = 0.f;
    for (int p = p0; p < p1; p++) {
      int s = g_srcT[p];
      if ((mb[s >> 5] >> (s & 31)) & 1u) {
        float vs = v[s];
        float w = expf(lrelu(fmaf(as2, vs, adt)) - m);
        den += w;
        num += w * vs;
      }
    }
    float sc = num / fmaxf(den, 1e-12f) + b2;
    scl[li] = sc;
    k32[li] = fenc(sc);
  }
  int kk = (nvv + 1) >> 1;
  if (tid == 0) { s_rem = kk; s_pfx = 0u; }
  __syncthreads();
  // radix-select the kk-th largest key (4 rounds of 8 bits)
  for (int r = 0; r < 4; r++) {
    int shift = 24 - 8 * r;
    hist[tid] = 0;
    __syncthreads();
    unsigned pfx = s_pfx;
    for (int li = tid; li < nvv; li += 256) {
      unsigned key = k32[li];
      bool cand = (r == 0) || ((key >> (shift + 8)) == pfx);
      if (cand) atomicAdd(&hist[(key >> shift) & 255], 1);
    }
    __syncthreads();
    if (tid < 32) {
      int s = 0;
      #pragma unroll
      for (int u = 0; u < 8; u++) s += hist[tid * 8 + u];
      int cum = s;
      #pragma unroll
      for (int o = 1; o < 32; o <<= 1) {
        int t2 = __shfl_down_sync(0xFFFFFFFFu, cum, o);
        if (tid + o < 32) cum += t2;
      }
      int run = cum - s;
      int rem = s_rem;
      unsigned pfxold = s_pfx;
      int fb = -1, frem = 0;
      for (int bb = tid * 8 + 7; bb >= tid * 8; bb--) {
        int h = hist[bb];
        if (run < rem && rem <= run + h) { fb = bb; frem = rem - run; }
        run += h;
      }
      __syncwarp();
      if (fb >= 0) { s_pfx = (pfxold << 8) | (unsigned)fb; s_rem = frem; }
    }
    __syncthreads();
  }
  unsigned T = s_pfx;
  int rem = s_rem;
  // keep: key > T, or key == T with tie-rank (ascending index) < rem
  for (int li = tid; li < nvv; li += 256) {
    unsigned key = k32[li];
    bool keep = key > T;
    if (!keep && key == T) {
      int cnt = 0;
      for (int l2 = 0; l2 < li; l2++) cnt += (k32[l2] == T);
      keep = cnt < rem;
    }
    if (keep) {
      int j = vlist[li];
      float sj = scl[li];
      out[i * N + j] = 1.f / (1.f + expf(-sj));
      if (wk) out[N * N + i * N + j] = 1.f;
    }
  }
}

// ---------------- launch: forked-capture graph ----------------
extern "C" void kernel_launch(void* const* d_in, const int* in_sizes, int n_in,
                              void* d_out, int out_size) {
  const float* x   = (const float*)d_in[0];
  const float* xo  = (const float*)d_in[1];
  const int*   ei  = (const int*)d_in[2];
  const float* W1  = (const float*)d_in[4];
  const float* a1  = (const float*)d_in[5];
  const float* a2  = (const float*)d_in[6];
  const float* b1  = (const float*)d_in[7];
  const float* w2  = (const float*)d_in[8];
  const float* as2 = (const float*)d_in[9];
  const float* ad2 = (const float*)d_in[10];
  const float* b2  = (const float*)d_in[11];
  float* out = (float*)d_out;
  int wk = (out_size >= 2 * N * N) ? 1 : 0;

  cudaEventRecord(g_hs.e0, 0);
  cudaStreamWaitEvent(g_hs.s1, g_hs.e0, 0);
  cudaStreamWaitEvent(g_hs.s2, g_hs.e0, 0);
  cudaStreamWaitEvent(g_hs.s3, g_hs.e0, 0);

  // s3: zero out + g_B
  kZero<<<512, 256, 0, g_hs.s3>>>(out, out_size);
  cudaEventRecord(g_hs.e3, g_hs.s3);

  // s1: vec1 -> sada
  kVec1<<<HD + N, 256, 0, g_hs.s1>>>(W1, a1, a2, b1, w2, xo);
  kSada<<<192, 256, 0, g_hs.s1>>>(x);
  cudaEventRecord(g_hs.e1, g_hs.s1);

  // s2: U partials -> U reduce
  kUp<<<24 * ZU, 256, 0, g_hs.s2>>>(W1, w2, xo);
  kUred<<<(HD * N) / 256, 256, 0, g_hs.s2>>>();
  cudaEventRecord(g_hs.e2, g_hs.s2);

  // s0 (default): critical path
  kCount<<<E2 / 256, 256>>>(ei);
  kScan<<<1, 256>>>();
  cudaStreamWaitEvent(0, g_hs.e3, 0);   // g_B zeroed before fill's atomicOr
  kFill<<<E2 / 256, 256>>>(ei);
  cudaStreamWaitEvent(0, g_hs.e1, 0);   // sada done before xg
  kXg<<<N, 128>>>(x);
  cudaStreamWaitEvent(0, g_hs.e2, 0);   // U ready before H2
  kH2<<<576, 256>>>();
  kF<<<N, 256>>>(as2, ad2, b2, out, wk);
}